// round 9
// baseline (speedup 1.0000x reference)
#include <cuda_runtime.h>

// B=4096, NSPIN=2, NPS=16, D=256, NION=8, DIM=3.  8192 (b,s) pairs.
// k0: G = A^T A per (s,i,o).  k1: GEMM+envelope -> M (row-major) to scratch.
// k2: warp-sync LU, 2 pairs/warp -> cofactors.

__device__ float g_M[8192 * 256];    // M per pair, row-major [n][o]
__device__ float g_G[2 * 8 * 16 * 12];

__global__ void k0_G(const float* __restrict__ edg)
{
    const int t = threadIdx.x;               // 256 = 2s * 8i * 16o
    const float* E = edg + t * 9;
    float e0=E[0],e1=E[1],e2=E[2],e3=E[3],e4=E[4],e5=E[5],e6=E[6],e7=E[7],e8=E[8];
    float* g = g_G + t * 12;
    g[0] = e0*e0 + e3*e3 + e6*e6;
    g[1] = e1*e1 + e4*e4 + e7*e7;
    g[2] = e2*e2 + e5*e5 + e8*e8;
    g[3] = 2.f*(e0*e1 + e3*e4 + e6*e7);
    g[4] = 2.f*(e0*e2 + e3*e5 + e6*e8);
    g[5] = 2.f*(e1*e2 + e4*e5 + e7*e8);
    g[6] = 0.f; g[7] = 0.f;
}

struct __align__(16) Smem1 {
    float xs[16 * 260];       // [n][d], pitch 260 (16.6 KB)
    float W[256 * 16];        // [d][chunk-rotated o] (16 KB)
    float part[16 * 16 * 16]; // [slice][n][o] (16 KB)
    float rs[16 * 24];        // [n][i*3+c]
    float rs2[1088];          // [n*68 + i*8 + c], c<6 products, c6..7 = 0
    float G[1536];            // [(i*16+o)*12 + c]
    float ei[8 * 16];
};

__global__ void __launch_bounds__(256, 3)
k1_buildM(const float* __restrict__ eq,  const float* __restrict__ rei,
          const float* __restrict__ Wg,  const float* __restrict__ bg,
          const float* __restrict__ eig)
{
    extern __shared__ __align__(16) char smem_raw[];
    Smem1& S = *reinterpret_cast<Smem1*>(smem_raw);
    const int p = blockIdx.x, s = p & 1, t = threadIdx.x;

    // ---- Phase 0: loads ----
    {
        const float* xsrc = eq + (size_t)p * 4096;
        #pragma unroll
        for (int c = 0; c < 4; ++c) {
            int idx = c * 1024 + t * 4;
            float4 v = *reinterpret_cast<const float4*>(xsrc + idx);
            int n = idx >> 8, d = idx & 255;
            *reinterpret_cast<float4*>(&S.xs[n * 260 + d]) = v;
        }
        const float* wsrc = Wg + s * 4096;
        #pragma unroll
        for (int c = 0; c < 4; ++c) {
            int idx = c * 1024 + t * 4;
            float4 v = *reinterpret_cast<const float4*>(wsrc + idx);
            int d = idx >> 4, o = idx & 15;       // o = 4*oq, float4 = one chunk
            int pc = ((o >> 2) + (d >> 3)) & 3;   // chunk rotation by kg
            *reinterpret_cast<float4*>(&S.W[d * 16 + pc * 4]) = v;
        }
        if (t < 96)
            *reinterpret_cast<float4*>(&S.rs[t*4]) =
                *reinterpret_cast<const float4*>(rei + (size_t)p*384 + t*4);
        #pragma unroll
        for (int k = 0; k < 6; ++k)
            S.G[t + k*256] = g_G[s*1536 + t + k*256];
        if (t < 128) S.ei[t] = eig[s*128 + t];
    }
    __syncthreads();

    // ---- Phase 1a: rs2 products (16n x 8i x 8c, c>=6 zero) ----
    {
        const int ca[6] = {0,1,2,0,0,1};
        const int cb[6] = {0,1,2,1,2,2};
        #pragma unroll
        for (int q = 0; q < 4; ++q) {
            int e = t*4 + q;                  // 0..1023
            int n = e >> 6, i = (e >> 3) & 7, c = e & 7;
            float v = 0.f;
            if (c < 6)
                v = S.rs[n*24 + i*3 + ca[c]] * S.rs[n*24 + i*3 + cb[c]];
            S.rs2[n*68 + i*8 + c] = v;
        }
    }

    // ---- Phase 1b: GEMM. 32 K-groups x 8 tiles (4n x 8o) ----
    const int kg = t >> 3, tt = t & 7;
    const int tn = (tt >> 1) << 2, to = (tt & 1) << 3;
    {
        const int toq = (tt & 1) << 1;                  // logical chunk of wa
        const int pca = (toq + kg) & 3, pcb = (toq + 1 + kg) & 3;
        const int d0 = kg << 3;
        const int jx = tt & 4;                          // xs bank de-collide
        float acc[4][8];
        #pragma unroll
        for (int r = 0; r < 4; ++r)
            #pragma unroll
            for (int c = 0; c < 8; ++c) acc[r][c] = 0.f;

        #pragma unroll
        for (int jj0 = 0; jj0 < 8; jj0 += 4) {
            const int db = d0 + (jj0 ^ jx);
            float4 xv[4];
            #pragma unroll
            for (int r = 0; r < 4; ++r)
                xv[r] = *reinterpret_cast<const float4*>(&S.xs[(tn+r)*260 + db]);
            #pragma unroll
            for (int u = 0; u < 4; ++u) {
                const int d = db + u;
                float4 wa = *reinterpret_cast<const float4*>(&S.W[d*16 + pca*4]);
                float4 wb = *reinterpret_cast<const float4*>(&S.W[d*16 + pcb*4]);
                #pragma unroll
                for (int r = 0; r < 4; ++r) {
                    float x = (&xv[r].x)[u];
                    acc[r][0]=fmaf(x,wa.x,acc[r][0]); acc[r][1]=fmaf(x,wa.y,acc[r][1]);
                    acc[r][2]=fmaf(x,wa.z,acc[r][2]); acc[r][3]=fmaf(x,wa.w,acc[r][3]);
                    acc[r][4]=fmaf(x,wb.x,acc[r][4]); acc[r][5]=fmaf(x,wb.y,acc[r][5]);
                    acc[r][6]=fmaf(x,wb.z,acc[r][6]); acc[r][7]=fmaf(x,wb.w,acc[r][7]);
                }
            }
        }
        const int slice = kg & 15;
        if (kg < 16) {
            #pragma unroll
            for (int r = 0; r < 4; ++r) {
                *reinterpret_cast<float4*>(&S.part[(slice*16 + tn + r)*16 + to]) =
                    make_float4(acc[r][0], acc[r][1], acc[r][2], acc[r][3]);
                *reinterpret_cast<float4*>(&S.part[(slice*16 + tn + r)*16 + to + 4]) =
                    make_float4(acc[r][4], acc[r][5], acc[r][6], acc[r][7]);
            }
        }
        __syncthreads();
        if (kg >= 16) {
            #pragma unroll
            for (int r = 0; r < 4; ++r) {
                float4* pa = reinterpret_cast<float4*>(&S.part[(slice*16 + tn + r)*16 + to]);
                float4* pb = pa + 1;
                float4 a = *pa, b = *pb;
                a.x += acc[r][0]; a.y += acc[r][1]; a.z += acc[r][2]; a.w += acc[r][3];
                b.x += acc[r][4]; b.y += acc[r][5]; b.z += acc[r][6]; b.w += acc[r][7];
                *pa = a; *pb = b;
            }
        }
        __syncthreads();
    }

    // ---- Phase 2: reduce + envelope + M (row-major, coalesced STG) ----
    {
        const int n = t >> 4, o = t & 15;
        float y = bg[s*16 + o];
        #pragma unroll
        for (int k = 0; k < 16; ++k) y += S.part[k*256 + t];

        float env = 0.f;
        #pragma unroll
        for (int i = 0; i < 8; ++i) {
            float4 Ga = *reinterpret_cast<const float4*>(&S.G[(i*16+o)*12]);
            float4 Gb = *reinterpret_cast<const float4*>(&S.G[(i*16+o)*12 + 4]);
            float4 Ra = *reinterpret_cast<const float4*>(&S.rs2[n*68 + i*8]);
            float4 Rb = *reinterpret_cast<const float4*>(&S.rs2[n*68 + i*8 + 4]);
            float q = Ga.x*Ra.x;
            q = fmaf(Ga.y, Ra.y, q);
            q = fmaf(Ga.z, Ra.z, q);
            q = fmaf(Ga.w, Ra.w, q);
            q = fmaf(Gb.x, Rb.x, q);
            q = fmaf(Gb.y, Rb.y, q);
            q = fmaxf(q, 0.f);
            env = fmaf(__expf(-sqrtf(q)), S.ei[i*16+o], env);
        }
        g_M[(size_t)p*256 + t] = y * env;   // M[n][o], t = n*16+o
    }
}

// ---- k2: warp-synchronous LU + solve; 2 pairs per warp, 16 lanes each ----
__global__ void __launch_bounds__(256)
k2_solve(float* __restrict__ out)
{
    const int t = threadIdx.x;
    const int w = t >> 5, g = (t >> 4) & 1, r = t & 15;
    const int p = blockIdx.x * 16 + w * 2 + g;
    const float* Mp = &g_M[(size_t)p * 256];

    float A[16];                       // lane r: A[j] = M^T[r][j] = M[j][r]
    #pragma unroll
    for (int j = 0; j < 16; ++j) A[j] = Mp[j*16 + r];
    float m0  = Mp[r*16];              // M[r][0]
    float rhs = (r == 0) ? 1.f : 0.f;  // e0
    int mystep = -1;
    float det = 1.f;
    unsigned remaining = 0xFFFFu, parity = 0;

    #pragma unroll
    for (int k = 0; k < 16; ++k) {
        float v = (mystep < 0) ? fabsf(A[k]) : -1.f;
        int idx = r;
        #pragma unroll
        for (int wd = 8; wd >= 1; wd >>= 1) {
            float ov = __shfl_xor_sync(0xFFFFFFFFu, v,   wd, 16);
            int   oi = __shfl_xor_sync(0xFFFFFFFFu, idx, wd, 16);
            if (ov > v || (ov == v && oi < idx)) { v = ov; idx = oi; }
        }
        const int pl = idx;
        const float pkk = __shfl_sync(0xFFFFFFFFu, A[k], pl, 16);
        det *= pkk;
        parity += __popc(remaining & ((1u << pl) - 1u));
        remaining &= ~(1u << pl);
        const bool active = (mystep < 0) && (r != pl);
        if (r == pl) mystep = k;
        const float f = __fdividef(A[k], pkk);
        #pragma unroll
        for (int j = k + 1; j < 16; ++j) {
            float pv = __shfl_sync(0xFFFFFFFFu, A[j], pl, 16);
            if (active) A[j] = fmaf(-f, pv, A[j]);
        }
        float pr = __shfl_sync(0xFFFFFFFFu, rhs, pl, 16);
        if (active) rhs = fmaf(-f, pr, rhs);
    }

    const float sdet = (parity & 1u) ? -det : det;
    float xk = 0.f;
    #pragma unroll
    for (int c = 15; c >= 0; --c) {
        unsigned b = __ballot_sync(0xFFFFFFFFu, mystep == c);
        int src = __ffs((b >> (g * 16)) & 0xFFFFu) - 1;
        float num = __shfl_sync(0xFFFFFFFFu, rhs,  src, 16);
        float den = __shfl_sync(0xFFFFFFFFu, A[c], src, 16);
        float xc  = __fdividef(num, den);
        if (r == c) xk = xc;
        if (mystep < c) rhs = fmaf(-A[c], xc, rhs);
    }
    out[(size_t)p * 16 + r] = m0 * sdet * xk;
}

extern "C" void kernel_launch(void* const* d_in, const int* in_sizes, int n_in,
                              void* d_out, int out_size) {
    const float* eq  = (const float*)d_in[0];
    const float* rei = (const float*)d_in[1];
    const float* Wg  = (const float*)d_in[2];
    const float* bg  = (const float*)d_in[3];
    const float* edg = (const float*)d_in[4];
    const float* eig = (const float*)d_in[5];
    float* out = (float*)d_out;
    const int smem = (int)sizeof(Smem1);
    cudaFuncSetAttribute(k1_buildM, cudaFuncAttributeMaxDynamicSharedMemorySize, smem);
    k0_G<<<1, 256>>>(edg);
    k1_buildM<<<8192, 256, smem>>>(eq, rei, Wg, bg, eig);
    k2_solve<<<512, 256>>>(out);
}